// round 8
// baseline (speedup 1.0000x reference)
#include <cuda_runtime.h>
#include <cuda_bf16.h>
#include <math.h>
#include <stdint.h>

#define BATCH 4096
#define KDIM  2048
#define NDIM  2048
#define DEPTH 16

// Quantization scales
#define S1F (6.5f / 127.0f)          // hi int8 scale (covers |x| <= 6.5)
#define S2F (0.015625f / 127.0f)     // residual int8 scale (bf16 half-ulp at |x|<8)
#define S1I (127.0f / 6.5f)
#define S2I (127.0f / 0.015625f)

// ---------------- device scratch (no allocation allowed) ----------------
__device__ __nv_bfloat16 g_Ahi[(size_t)BATCH * KDIM];   // bf16 hi of x, [M][K]
__device__ int8_t        g_Ahi8[(size_t)BATCH * KDIM];  // round(ahi/S1), [M][K]
__device__ int8_t        g_Ar8 [(size_t)BATCH * KDIM];  // round((a-ahi)/S2), [M][K]
__device__ __nv_bfloat16 g_Bhi[(size_t)KDIM * NDIM];    // bf16 hi of W, [K][N]
__device__ int8_t        g_B8f [(size_t)NDIM * KDIM];   // round(b/S1), TRANSPOSED [N][K]
__device__ int8_t        g_Br8 [(size_t)NDIM * KDIM];   // round((b-bhi)/S2), [N][K]
__device__ float g_padd[NDIM];                          // bias + probs

__device__ __forceinline__ int qclamp(float x, float inv) {
    int t = __float2int_rn(x * inv);
    return t < -127 ? -127 : (t > 127 ? 127 : t);
}

// ---------------- probs + bias ----------------
// probs[j] = (prod_{d,g} cos(W[d,j,g]))^2 / DIN  (uniform state kills the sin terms)
__global__ void probs_kernel(const float* __restrict__ W,
                             const float* __restrict__ bias) {
    int j = blockIdx.x * blockDim.x + threadIdx.x;
    if (j >= NDIM) return;
    float p = 1.0f;
#pragma unroll
    for (int d = 0; d < DEPTH; ++d) {
        const float* base = W + ((size_t)d * KDIM + j) * NDIM;
        p *= cosf(base[0]);
        p *= cosf(base[1]);
        p *= cosf(base[2]);
    }
    g_padd[j] = bias[j] + (p * p) * (1.0f / (float)KDIM);
}

// ---------------- prep A: bf16 hi + int8 (hi, residual) ----------------
__global__ void prepA_kernel(const float* __restrict__ src,
                             __nv_bfloat16* __restrict__ hi,
                             char4* __restrict__ hi8, char4* __restrict__ r8) {
    int i = blockIdx.x * blockDim.x + threadIdx.x;   // one float4 per thread
    float4 v = ((const float4*)src)[i];
    __nv_bfloat16 h0 = __float2bfloat16_rn(v.x), h1 = __float2bfloat16_rn(v.y);
    __nv_bfloat16 h2 = __float2bfloat16_rn(v.z), h3 = __float2bfloat16_rn(v.w);
    float f0 = __bfloat162float(h0), f1 = __bfloat162float(h1);
    float f2 = __bfloat162float(h2), f3 = __bfloat162float(h3);
    __nv_bfloat162* hp = (__nv_bfloat162*)(hi + 4 * (size_t)i);
    hp[0] = __nv_bfloat162(h0, h1);
    hp[1] = __nv_bfloat162(h2, h3);
    hi8[i] = make_char4((char)qclamp(f0, S1I), (char)qclamp(f1, S1I),
                        (char)qclamp(f2, S1I), (char)qclamp(f3, S1I));
    r8[i]  = make_char4((char)qclamp(v.x - f0, S2I), (char)qclamp(v.y - f1, S2I),
                        (char)qclamp(v.z - f2, S2I), (char)qclamp(v.w - f3, S2I));
}

// ---------------- prep B: bf16 hi [K][N] + transposed int8 [N][K] ----------------
__global__ void prepB_kernel(const float* __restrict__ w,
                             __nv_bfloat16* __restrict__ bhi,
                             int8_t* __restrict__ b8f, int8_t* __restrict__ br8) {
    __shared__ float t[32][33];
    const int n0 = blockIdx.x * 32, k0 = blockIdx.y * 32;
    const int tx = threadIdx.x, ty = threadIdx.y;   // block (32, 8)
#pragma unroll
    for (int i = 0; i < 32; i += 8) {
        float v = w[(size_t)(k0 + ty + i) * NDIM + n0 + tx];
        t[ty + i][tx] = v;
        bhi[(size_t)(k0 + ty + i) * NDIM + n0 + tx] = __float2bfloat16_rn(v);
    }
    __syncthreads();
#pragma unroll
    for (int i = 0; i < 32; i += 8) {
        float v = t[tx][ty + i];                    // = w[k0+tx][n0+ty+i]
        float hv = __bfloat162float(__float2bfloat16_rn(v));
        size_t o = (size_t)(n0 + ty + i) * KDIM + k0 + tx;
        b8f[o] = (int8_t)qclamp(v, S1I);            // full b quantized
        br8[o] = (int8_t)qclamp(v - hv, S2I);       // residual quantized
    }
}

// ---------------- hybrid GEMM + tanh ----------------
// z = Ahi*Bhi (bf16 HMMA, fp32 acc)  +  S1*S2*( Ar8*B8f + Ahi8*Br8 ) (IMMA, s32 acc)
#define BM 128
#define BN 128
#define BK 64
#define NK (KDIM / BK)       // 32
#define NT 256

// smem stage layout (bytes)
#define ROWA_B 144           // 64 bf16 = 128B data + 16 pad (stride 9 chunks: conflict-free)
#define ROWB_B 272           // 128 bf16 = 256B data + 16 pad (stride 17)
#define ROW8_B 80            // 64 int8 = 64B data + 16 pad (stride 20 words: conflict-free)
#define AH_OFF  0
#define BH_OFF  18432        // 128*144
#define A8H_OFF 35840        // +64*272
#define A8R_OFF 46080        // +128*80
#define B8F_OFF 56320
#define B8R_OFF 66560
#define STAGE_B 76800
#define SMEM_TOTAL (2 * STAGE_B)   // 153600

__device__ __forceinline__ void cp16(uint32_t dst, const void* src) {
    asm volatile("cp.async.cg.shared.global [%0], [%1], 16;\n" ::"r"(dst), "l"(src));
}
__device__ __forceinline__ uint32_t lds32(uint32_t a) {
    uint32_t v;
    asm("ld.shared.b32 %0, [%1];" : "=r"(v) : "r"(a));
    return v;
}
#define LDSM4(R, ADDR)                                                           \
    asm volatile("ldmatrix.sync.aligned.m8n8.x4.shared.b16 {%0,%1,%2,%3}, [%4];" \
                 : "=r"(R[0]), "=r"(R[1]), "=r"(R[2]), "=r"(R[3]) : "r"(ADDR))
#define LDSM4T(R, ADDR)                                                                \
    asm volatile("ldmatrix.sync.aligned.m8n8.x4.trans.shared.b16 {%0,%1,%2,%3}, [%4];" \
                 : "=r"(R[0]), "=r"(R[1]), "=r"(R[2]), "=r"(R[3]) : "r"(ADDR))
#define MMA(C, A, B0, B1)                                               \
    asm volatile("mma.sync.aligned.m16n8k16.row.col.f32.bf16.bf16.f32 " \
                 "{%0,%1,%2,%3},{%4,%5,%6,%7},{%8,%9},{%0,%1,%2,%3};"   \
                 : "+f"(C[0]), "+f"(C[1]), "+f"(C[2]), "+f"(C[3])       \
                 : "r"(A[0]), "r"(A[1]), "r"(A[2]), "r"(A[3]), "r"(B0), "r"(B1))
#define IMMA(C, A, B0, B1)                                              \
    asm volatile("mma.sync.aligned.m16n8k32.row.col.s32.s8.s8.s32 "     \
                 "{%0,%1,%2,%3},{%4,%5,%6,%7},{%8,%9},{%0,%1,%2,%3};"   \
                 : "+r"(C[0]), "+r"(C[1]), "+r"(C[2]), "+r"(C[3])       \
                 : "r"(A[0]), "r"(A[1]), "r"(A[2]), "r"(A[3]), "r"(B0), "r"(B1))

__global__ __launch_bounds__(NT, 1) void gemm_tanh_kernel(float* __restrict__ out) {
    extern __shared__ char smem[];
    const uint32_t sbase = (uint32_t)__cvta_generic_to_shared(smem);

    const int tid  = threadIdx.x;
    const int lane = tid & 31;
    const int wid  = tid >> 5;
    const int wm = (wid & 1) * 64;    // 2 warps over M
    const int wn = (wid >> 1) * 32;   // 4 warps over N
    const int bm = blockIdx.y * BM;
    const int bn = blockIdx.x * BN;

    const __nv_bfloat16* Ah  = g_Ahi  + (size_t)bm * KDIM;
    const int8_t*        A8h = g_Ahi8 + (size_t)bm * KDIM;
    const int8_t*        A8r = g_Ar8  + (size_t)bm * KDIM;
    const __nv_bfloat16* Bh  = g_Bhi  + bn;
    const int8_t*        B8f = g_B8f  + (size_t)bn * KDIM;
    const int8_t*        B8r = g_Br8  + (size_t)bn * KDIM;

    float accF[4][4][4];
    int   accS[4][4][4];
#pragma unroll
    for (int i = 0; i < 4; ++i)
#pragma unroll
        for (int j = 0; j < 4; ++j)
#pragma unroll
            for (int k = 0; k < 4; ++k) { accF[i][j][k] = 0.0f; accS[i][j][k] = 0; }

    const int r16 = lane & 15, h4 = lane >> 4;
    const int g = lane >> 2, tig = lane & 3;
    const uint32_t a_base  = (uint32_t)((wm + r16) * ROWA_B + h4 * 16);
    const uint32_t b_base  = (uint32_t)(r16 * ROWB_B + (wn + 8 * h4) * 2);
    const uint32_t a8_base = (uint32_t)((wm + g) * ROW8_B + 4 * tig);
    const uint32_t b8_base = (uint32_t)((wn + g) * ROW8_B + 4 * tig);

    auto load_stage = [&](int s, int kt) {
        const uint32_t st = sbase + s * STAGE_B;
        const int k0 = kt * BK;
        // bf16 A: 128 rows x 8 chunks
#pragma unroll
        for (int i = 0; i < 4; ++i) {
            const int f = tid + i * NT;
            const int r = f >> 3, c = f & 7;
            cp16(st + AH_OFF + r * ROWA_B + c * 16, Ah + (size_t)r * KDIM + k0 + c * 8);
        }
        // bf16 B: 64 rows x 16 chunks
#pragma unroll
        for (int i = 0; i < 4; ++i) {
            const int f = tid + i * NT;
            const int r = f >> 4, c = f & 15;
            cp16(st + BH_OFF + r * ROWB_B + c * 16, Bh + (size_t)(k0 + r) * NDIM + c * 8);
        }
        // int8 A hi / residual: 128 rows x 4 chunks each
#pragma unroll
        for (int i = 0; i < 2; ++i) {
            const int f = tid + i * NT;
            const int r = f >> 2, c = f & 3;
            const uint32_t so = (uint32_t)(r * ROW8_B + c * 16);
            const size_t go = (size_t)r * KDIM + k0 + c * 16;
            cp16(st + A8H_OFF + so, A8h + go);
            cp16(st + A8R_OFF + so, A8r + go);
        }
        // int8 B full / residual (transposed [N][K]): 128 rows x 4 chunks each
#pragma unroll
        for (int i = 0; i < 2; ++i) {
            const int f = tid + i * NT;
            const int r = f >> 2, c = f & 3;
            const uint32_t so = (uint32_t)(r * ROW8_B + c * 16);
            const size_t go = (size_t)r * KDIM + k0 + c * 16;
            cp16(st + B8F_OFF + so, B8f + go);
            cp16(st + B8R_OFF + so, B8r + go);
        }
    };

    load_stage(0, 0);
    asm volatile("cp.async.commit_group;\n");

    for (int kt = 0; kt < NK; ++kt) {
        const int s = kt & 1;
        asm volatile("cp.async.wait_group 0;\n");
        __syncthreads();

        if (kt + 1 < NK) {
            load_stage(s ^ 1, kt + 1);
            asm volatile("cp.async.commit_group;\n");
        }

        const uint32_t st = sbase + s * STAGE_B;
#pragma unroll
        for (int k32 = 0; k32 < 2; ++k32) {
            // ---- int8 fragments (plain LDS.32, layout matches IMMA) ----
            uint32_t a8h[4][4], a8r[4][4], b8fr[4][2], b8rr[4][2];
#pragma unroll
            for (int mi = 0; mi < 4; ++mi) {
                const uint32_t ad = st + a8_base + mi * (16 * ROW8_B) + k32 * 32;
                a8h[mi][0] = lds32(ad + A8H_OFF);
                a8h[mi][1] = lds32(ad + A8H_OFF + 8 * ROW8_B);
                a8h[mi][2] = lds32(ad + A8H_OFF + 16);
                a8h[mi][3] = lds32(ad + A8H_OFF + 8 * ROW8_B + 16);
                a8r[mi][0] = lds32(ad + A8R_OFF);
                a8r[mi][1] = lds32(ad + A8R_OFF + 8 * ROW8_B);
                a8r[mi][2] = lds32(ad + A8R_OFF + 16);
                a8r[mi][3] = lds32(ad + A8R_OFF + 8 * ROW8_B + 16);
            }
#pragma unroll
            for (int n8 = 0; n8 < 4; ++n8) {
                const uint32_t bd = st + b8_base + n8 * (8 * ROW8_B) + k32 * 32;
                b8fr[n8][0] = lds32(bd + B8F_OFF);
                b8fr[n8][1] = lds32(bd + B8F_OFF + 16);
                b8rr[n8][0] = lds32(bd + B8R_OFF);
                b8rr[n8][1] = lds32(bd + B8R_OFF + 16);
            }
            // ---- bf16 hi*hi: 2 x (k16 frags + 16 HMMA) ----
#pragma unroll
            for (int kk = 0; kk < 2; ++kk) {
                const int k16 = k32 * 32 + kk * 16;
                uint32_t ah[4][4], bh[2][4];
#pragma unroll
                for (int mi = 0; mi < 4; ++mi)
                    LDSM4(ah[mi], st + AH_OFF + a_base + mi * 16 * ROWA_B + k16 * 2);
#pragma unroll
                for (int n16 = 0; n16 < 2; ++n16)
                    LDSM4T(bh[n16], st + BH_OFF + b_base + k16 * ROWB_B + n16 * 32);
#pragma unroll
                for (int n16 = 0; n16 < 2; ++n16)
#pragma unroll
                    for (int mi = 0; mi < 4; ++mi) {
                        MMA(accF[mi][2 * n16 + 0], ah[mi], bh[n16][0], bh[n16][1]);
                        MMA(accF[mi][2 * n16 + 1], ah[mi], bh[n16][2], bh[n16][3]);
                    }
            }
            // ---- int8 corrections: ra*b  then  ahi*rb (shared s32 acc) ----
#pragma unroll
            for (int n8 = 0; n8 < 4; ++n8)
#pragma unroll
                for (int mi = 0; mi < 4; ++mi)
                    IMMA(accS[mi][n8], a8r[mi], b8fr[n8][0], b8fr[n8][1]);
#pragma unroll
            for (int n8 = 0; n8 < 4; ++n8)
#pragma unroll
                for (int mi = 0; mi < 4; ++mi)
                    IMMA(accS[mi][n8], a8h[mi], b8rr[n8][0], b8rr[n8][1]);
        }
    }

    // ---------------- epilogue: combine + (bias+probs), tanh ----------------
    const float SC = S1F * S2F;
    float2 badd[4];
#pragma unroll
    for (int ni = 0; ni < 4; ++ni)
        badd[ni] = *(const float2*)(g_padd + bn + wn + ni * 8 + 2 * tig);
#pragma unroll
    for (int mi = 0; mi < 4; ++mi) {
        const int row0 = bm + wm + mi * 16 + g;
#pragma unroll
        for (int ni = 0; ni < 4; ++ni) {
            const int col = bn + wn + ni * 8 + 2 * tig;
            float2 v0, v1;
            v0.x = tanhf(accF[mi][ni][0] + SC * (float)accS[mi][ni][0] + badd[ni].x);
            v0.y = tanhf(accF[mi][ni][1] + SC * (float)accS[mi][ni][1] + badd[ni].y);
            v1.x = tanhf(accF[mi][ni][2] + SC * (float)accS[mi][ni][2] + badd[ni].x);
            v1.y = tanhf(accF[mi][ni][3] + SC * (float)accS[mi][ni][3] + badd[ni].y);
            *(float2*)(out + (size_t)row0 * NDIM + col) = v0;
            *(float2*)(out + (size_t)(row0 + 8) * NDIM + col) = v1;
        }
    }
}

// ---------------- launch ----------------
extern "C" void kernel_launch(void* const* d_in, const int* in_sizes, int n_in,
                              void* d_out, int out_size) {
    (void)in_sizes; (void)n_in; (void)out_size;
    const float* x  = (const float*)d_in[0];
    const float* aw = (const float*)d_in[1];
    const float* cw = (const float*)d_in[2];
    const float* cb = (const float*)d_in[3];
    float* out = (float*)d_out;

    static bool attr_done = false;
    if (!attr_done) {
        cudaFuncSetAttribute(gemm_tanh_kernel,
                             cudaFuncAttributeMaxDynamicSharedMemorySize, SMEM_TOTAL);
        attr_done = true;
    }

    __nv_bfloat16 *ahi, *bhi;
    int8_t *ahi8, *ar8, *b8f, *br8;
    cudaGetSymbolAddress((void**)&ahi,  g_Ahi);
    cudaGetSymbolAddress((void**)&ahi8, g_Ahi8);
    cudaGetSymbolAddress((void**)&ar8,  g_Ar8);
    cudaGetSymbolAddress((void**)&bhi,  g_Bhi);
    cudaGetSymbolAddress((void**)&b8f,  g_B8f);
    cudaGetSymbolAddress((void**)&br8,  g_Br8);

    prepA_kernel<<<(BATCH * KDIM / 4) / 256, 256>>>(x, ahi, (char4*)ahi8, (char4*)ar8);
    prepB_kernel<<<dim3(NDIM / 32, KDIM / 32), dim3(32, 8)>>>(cw, bhi, b8f, br8);
    probs_kernel<<<NDIM / 256, 256>>>(aw, cb);

    dim3 grid(NDIM / BN, BATCH / BM);
    gemm_tanh_kernel<<<grid, NT, SMEM_TOTAL>>>(out);
}

// round 9
// speedup vs baseline: 2.3428x; 2.3428x over previous
#include <cuda_runtime.h>
#include <cuda_bf16.h>
#include <math.h>
#include <stdint.h>

#define BATCH 4096
#define KDIM  2048
#define NDIM  2048
#define DEPTH 16

// ---------------- device scratch (no allocation allowed) ----------------
__device__ __nv_bfloat16 g_Ahi[(size_t)BATCH * KDIM];
__device__ __nv_bfloat16 g_Alo[(size_t)BATCH * KDIM];
__device__ __nv_bfloat16 g_Bhi[(size_t)KDIM * NDIM];
__device__ __nv_bfloat16 g_Blo[(size_t)KDIM * NDIM];
__device__ float g_padd[NDIM];   // bias + probs, fused

// ---------------- fused prep: A-split | B-split | probs ----------------
#define A4BLKS 8192              // BATCH*KDIM/4/256
#define B4BLKS 4096              // KDIM*NDIM/4/256
#define PRBLKS 8                 // NDIM/256
__device__ __forceinline__ void split4(const float* __restrict__ src,
                                       __nv_bfloat16* __restrict__ hi,
                                       __nv_bfloat16* __restrict__ lo, int i) {
    float4 v = ((const float4*)src)[i];
    __nv_bfloat16 h0 = __float2bfloat16_rn(v.x), h1 = __float2bfloat16_rn(v.y);
    __nv_bfloat16 h2 = __float2bfloat16_rn(v.z), h3 = __float2bfloat16_rn(v.w);
    __nv_bfloat16 l0 = __float2bfloat16_rn(v.x - __bfloat162float(h0));
    __nv_bfloat16 l1 = __float2bfloat16_rn(v.y - __bfloat162float(h1));
    __nv_bfloat16 l2 = __float2bfloat16_rn(v.z - __bfloat162float(h2));
    __nv_bfloat16 l3 = __float2bfloat16_rn(v.w - __bfloat162float(h3));
    __nv_bfloat162* hp = (__nv_bfloat162*)(hi + 4 * (size_t)i);
    __nv_bfloat162* lp = (__nv_bfloat162*)(lo + 4 * (size_t)i);
    hp[0] = __nv_bfloat162(h0, h1); hp[1] = __nv_bfloat162(h2, h3);
    lp[0] = __nv_bfloat162(l0, l1); lp[1] = __nv_bfloat162(l2, l3);
}

__global__ void prep_kernel(const float* __restrict__ x,
                            const float* __restrict__ cw,
                            const float* __restrict__ aw,
                            const float* __restrict__ cb,
                            __nv_bfloat16* __restrict__ ahi,
                            __nv_bfloat16* __restrict__ alo,
                            __nv_bfloat16* __restrict__ bhi,
                            __nv_bfloat16* __restrict__ blo) {
    const int b = blockIdx.x, t = threadIdx.x;
    if (b < A4BLKS) {
        split4(x, ahi, alo, b * 256 + t);
    } else if (b < A4BLKS + B4BLKS) {
        split4(cw, bhi, blo, (b - A4BLKS) * 256 + t);
    } else {
        // probs[j] = (prod cos W[d,j,g])^2 / DIN  (uniform state kills sin terms)
        const int j = (b - A4BLKS - B4BLKS) * 256 + t;
        float p = 1.0f;
#pragma unroll
        for (int d = 0; d < DEPTH; ++d) {
            const float* base = aw + ((size_t)d * KDIM + j) * NDIM;
            p *= cosf(base[0]);
            p *= cosf(base[1]);
            p *= cosf(base[2]);
        }
        g_padd[j] = cb[j] + (p * p) * (1.0f / (float)KDIM);
    }
}

// ---------------- tensor-core GEMM + tanh ----------------
// out = tanh( Ahi*Bhi + Ahi*Blo + Alo*Bhi + padd )
#define BM 128
#define BN 256
#define BK 32
#define NK (KDIM / BK)       // 64
#define NSTAGE 4

// padded smem rows: 16B-chunk strides 5 (A) and 33 (B) -> conflict-free ldmatrix
#define ROWA_B 80                            // 32 bf16 = 64B data, pad to 80B
#define ROWB_B 528                           // 256 bf16 = 512B data, pad to 528B
#define AHI_OFF 0
#define ALO_OFF (128 * ROWA_B)               // 10240
#define BHI_OFF (2 * 128 * ROWA_B)           // 20480
#define BLO_OFF (BHI_OFF + 32 * ROWB_B)      // 37376
#define STAGE_B (BHI_OFF + 2 * 32 * ROWB_B)  // 54272
#define SMEM_TOTAL (NSTAGE * STAGE_B)        // 217088

__device__ __forceinline__ void cp16(uint32_t dst, const void* src) {
    asm volatile("cp.async.cg.shared.global [%0], [%1], 16;\n" ::"r"(dst), "l"(src));
}
#define LDSM4(R, ADDR)                                                           \
    asm volatile("ldmatrix.sync.aligned.m8n8.x4.shared.b16 {%0,%1,%2,%3}, [%4];" \
                 : "=r"(R[0]), "=r"(R[1]), "=r"(R[2]), "=r"(R[3]) : "r"(ADDR))
#define LDSM4T(R, ADDR)                                                                \
    asm volatile("ldmatrix.sync.aligned.m8n8.x4.trans.shared.b16 {%0,%1,%2,%3}, [%4];" \
                 : "=r"(R[0]), "=r"(R[1]), "=r"(R[2]), "=r"(R[3]) : "r"(ADDR))
#define MMA(C, A, B0, B1)                                               \
    asm volatile("mma.sync.aligned.m16n8k16.row.col.f32.bf16.bf16.f32 " \
                 "{%0,%1,%2,%3},{%4,%5,%6,%7},{%8,%9},{%0,%1,%2,%3};"   \
                 : "+f"(C[0]), "+f"(C[1]), "+f"(C[2]), "+f"(C[3])       \
                 : "r"(A[0]), "r"(A[1]), "r"(A[2]), "r"(A[3]), "r"(B0), "r"(B1))

__global__ __launch_bounds__(256, 1) void gemm_tanh_kernel(float* __restrict__ out) {
    extern __shared__ char smem[];
    const uint32_t sbase = (uint32_t)__cvta_generic_to_shared(smem);

    const int tid  = threadIdx.x;
    const int lane = tid & 31;
    const int wid  = tid >> 5;
    const int wm = (wid & 1) * 64;    // 2 warps over M (64-row tiles)
    const int wn = (wid >> 1) * 64;   // 4 warps over N (64-col tiles)
    const int bm = blockIdx.y * BM;
    const int bn = blockIdx.x * BN;

    const __nv_bfloat16* Ah = g_Ahi + (size_t)bm * KDIM;
    const __nv_bfloat16* Al = g_Alo + (size_t)bm * KDIM;
    const __nv_bfloat16* Bh = g_Bhi + bn;
    const __nv_bfloat16* Bl = g_Blo + bn;

    float acc[4][8][4];
#pragma unroll
    for (int i = 0; i < 4; ++i)
#pragma unroll
        for (int j = 0; j < 8; ++j)
#pragma unroll
            for (int k = 0; k < 4; ++k) acc[i][j][k] = 0.0f;

    // ldmatrix base addresses (byte offsets within a stage)
    const int r16 = lane & 15, h4 = lane >> 4;
    const uint32_t a_base = (uint32_t)((wm + r16) * ROWA_B + h4 * 16);
    const uint32_t b_base = (uint32_t)(r16 * ROWB_B + (wn + 8 * h4) * 2);

    auto load_stage = [&](int s, int kt) {
        const uint32_t st = sbase + s * STAGE_B;
        const int k0 = kt * BK;
        // A hi/lo: 128 rows x 4 chunks of 16B (512 chunks, 2 per thread)
#pragma unroll
        for (int i = 0; i < 2; ++i) {
            const int f = tid + i * 256;
            const int r = f >> 2, c = f & 3;
            const uint32_t so = (uint32_t)(r * ROWA_B + c * 16);
            const size_t go = (size_t)r * KDIM + k0 + c * 8;
            cp16(st + AHI_OFF + so, Ah + go);
            cp16(st + ALO_OFF + so, Al + go);
        }
        // B hi/lo: 32 rows x 32 chunks of 16B (1024 chunks, 4 per thread)
#pragma unroll
        for (int i = 0; i < 4; ++i) {
            const int f = tid + i * 256;
            const int r = f >> 5, c = f & 31;
            const uint32_t so = (uint32_t)(r * ROWB_B + c * 16);
            const size_t go = (size_t)(k0 + r) * NDIM + c * 8;
            cp16(st + BHI_OFF + so, Bh + go);
            cp16(st + BLO_OFF + so, Bl + go);
        }
    };

    // prologue: fill 3 of 4 stages
    load_stage(0, 0);
    asm volatile("cp.async.commit_group;\n");
    load_stage(1, 1);
    asm volatile("cp.async.commit_group;\n");
    load_stage(2, 2);
    asm volatile("cp.async.commit_group;\n");

    for (int kt = 0; kt < NK; ++kt) {
        const int s = kt & 3;
        // stage s (group kt) must have landed; keep up to 2 younger groups in flight
        if (kt + 3 < NK) asm volatile("cp.async.wait_group 2;\n");
        else             asm volatile("cp.async.wait_group 0;\n");
        __syncthreads();

        // refill the stage freed at kt-1 (barrier above guarantees it's consumed)
        if (kt + 3 < NK) {
            load_stage((kt + 3) & 3, kt + 3);
            asm volatile("cp.async.commit_group;\n");
        }

        const uint32_t st = sbase + s * STAGE_B;
#pragma unroll
        for (int k16 = 0; k16 < BK / 16; ++k16) {
            // ---- front-load ALL fragments for this k16 (16 LDSM.x4) ----
            uint32_t ah[4][4], al[4][4], bh[4][4], bl[4][4];
#pragma unroll
            for (int mi = 0; mi < 4; ++mi) {
                const uint32_t ad = st + a_base + mi * 16 * ROWA_B + k16 * 32;
                LDSM4(ah[mi], ad + AHI_OFF);
                LDSM4(al[mi], ad + ALO_OFF);
            }
#pragma unroll
            for (int n16 = 0; n16 < 4; ++n16) {
                const uint32_t bd = st + b_base + k16 * 16 * ROWB_B + n16 * 32;
                LDSM4T(bh[n16], bd + BHI_OFF);
                LDSM4T(bl[n16], bd + BLO_OFF);
            }
            // ---- 96 uninterrupted MMAs, pass-major ----
#pragma unroll
            for (int n16 = 0; n16 < 4; ++n16)
#pragma unroll
                for (int mi = 0; mi < 4; ++mi) {
                    MMA(acc[mi][2 * n16 + 0], ah[mi], bh[n16][0], bh[n16][1]);
                    MMA(acc[mi][2 * n16 + 1], ah[mi], bh[n16][2], bh[n16][3]);
                }
#pragma unroll
            for (int n16 = 0; n16 < 4; ++n16)
#pragma unroll
                for (int mi = 0; mi < 4; ++mi) {
                    MMA(acc[mi][2 * n16 + 0], ah[mi], bl[n16][0], bl[n16][1]);
                    MMA(acc[mi][2 * n16 + 1], ah[mi], bl[n16][2], bl[n16][3]);
                }
#pragma unroll
            for (int n16 = 0; n16 < 4; ++n16)
#pragma unroll
                for (int mi = 0; mi < 4; ++mi) {
                    MMA(acc[mi][2 * n16 + 0], al[mi], bh[n16][0], bh[n16][1]);
                    MMA(acc[mi][2 * n16 + 1], al[mi], bh[n16][2], bh[n16][3]);
                }
        }
    }

    // ---------------- epilogue: + (bias+probs), tanh ----------------
    const int g = lane >> 2, tig = lane & 3;
    float2 badd[8];
#pragma unroll
    for (int ni = 0; ni < 8; ++ni)
        badd[ni] = *(const float2*)(g_padd + bn + wn + ni * 8 + 2 * tig);
#pragma unroll
    for (int mi = 0; mi < 4; ++mi) {
        const int row0 = bm + wm + mi * 16 + g;
#pragma unroll
        for (int ni = 0; ni < 8; ++ni) {
            const int col = bn + wn + ni * 8 + 2 * tig;
            float2 v0, v1;
            v0.x = tanhf(acc[mi][ni][0] + badd[ni].x);
            v0.y = tanhf(acc[mi][ni][1] + badd[ni].y);
            v1.x = tanhf(acc[mi][ni][2] + badd[ni].x);
            v1.y = tanhf(acc[mi][ni][3] + badd[ni].y);
            *(float2*)(out + (size_t)row0 * NDIM + col) = v0;
            *(float2*)(out + (size_t)(row0 + 8) * NDIM + col) = v1;
        }
    }
}

// ---------------- launch ----------------
extern "C" void kernel_launch(void* const* d_in, const int* in_sizes, int n_in,
                              void* d_out, int out_size) {
    (void)in_sizes; (void)n_in; (void)out_size;
    const float* x  = (const float*)d_in[0];
    const float* aw = (const float*)d_in[1];
    const float* cw = (const float*)d_in[2];
    const float* cb = (const float*)d_in[3];
    float* out = (float*)d_out;

    static bool attr_done = false;
    if (!attr_done) {
        cudaFuncSetAttribute(gemm_tanh_kernel,
                             cudaFuncAttributeMaxDynamicSharedMemorySize, SMEM_TOTAL);
        attr_done = true;
    }

    __nv_bfloat16 *ahi, *alo, *bhi, *blo;
    cudaGetSymbolAddress((void**)&ahi, g_Ahi);
    cudaGetSymbolAddress((void**)&alo, g_Alo);
    cudaGetSymbolAddress((void**)&bhi, g_Bhi);
    cudaGetSymbolAddress((void**)&blo, g_Blo);

    prep_kernel<<<A4BLKS + B4BLKS + PRBLKS, 256>>>(x, cw, aw, cb, ahi, alo, bhi, blo);

    dim3 grid(NDIM / BN, BATCH / BM);
    gemm_tanh_kernel<<<grid, 256, SMEM_TOTAL>>>(out);
}